// round 7
// baseline (speedup 1.0000x reference)
#include <cuda_runtime.h>
#include <cuda_fp16.h>
#include <math.h>
#include <float.h>

#define NOFF 20
#define HDIM 128
#define SEQN 8192
#define NH   16
#define NB   2
#define WARPS 8
#define ITERS 4                        // 2 queries/warp/iter -> 8*2*4 = 64 queries/block
#define TOTE (NB * NH * SEQN * HDIM)   // 33554432 elements

__constant__ int c_offs[NOFF] = {1,2,3,4,5,6,7,8,9,11,13,15,16,23,32,64,128,256,512,1024};

// fp16 mirrors of k and v (static device scratch; allocation-free)
__device__ __half g_kh[TOTE];
__device__ __half g_vh[TOTE];

__device__ __forceinline__ unsigned long long f2add(unsigned long long a, unsigned long long b) {
    unsigned long long d;
    asm("add.rn.f32x2 %0, %1, %2;" : "=l"(d) : "l"(a), "l"(b));
    return d;
}
__device__ __forceinline__ unsigned long long f2pack(float lo, float hi) {
    unsigned long long d;
    asm("mov.b64 %0, {%1, %2};" : "=l"(d) : "f"(lo), "f"(hi));
    return d;
}
__device__ __forceinline__ float2 f2unpack(unsigned long long a) {
    float lo, hi;
    asm("mov.b64 {%0, %1}, %2;" : "=f"(lo), "=f"(hi) : "l"(a));
    return make_float2(lo, hi);
}
__device__ __forceinline__ unsigned int h2u(__half2 h) {
    union { __half2 h; unsigned int u; } c; c.h = h; return c.u;
}

// ---- pre-pass: fp32 k,v -> fp16 mirrors; evict-first reads keep L2 for mirrors ----
__global__ void __launch_bounds__(256) cvt_kv(const float* __restrict__ k, const float* __restrict__ v)
{
    const int total4 = TOTE / 4;
    for (int i = blockIdx.x * blockDim.x + threadIdx.x; i < total4; i += gridDim.x * blockDim.x) {
        float4 a = __ldcs(((const float4*)k) + i);
        uint2 ka;
        ka.x = h2u(__floats2half2_rn(a.x, a.y));
        ka.y = h2u(__floats2half2_rn(a.z, a.w));
        ((uint2*)g_kh)[i] = ka;
        float4 b = __ldcs(((const float4*)v) + i);
        uint2 vb2;
        vb2.x = h2u(__floats2half2_rn(b.x, b.y));
        vb2.y = h2u(__floats2half2_rn(b.z, b.w));
        ((uint2*)g_vh)[i] = vb2;
    }
}

__device__ __forceinline__ void dot8(float& acc, float4 qa, float4 qb, uint4 kk) {
    const float2 f0 = __half22float2(*(const __half2*)&kk.x);
    const float2 f1 = __half22float2(*(const __half2*)&kk.y);
    const float2 f2 = __half22float2(*(const __half2*)&kk.z);
    const float2 f3 = __half22float2(*(const __half2*)&kk.w);
    acc = fmaf(qa.x, f0.x, fmaf(qa.y, f0.y, fmaf(qa.z, f1.x, fmaf(qa.w, f1.y,
          fmaf(qb.x, f2.x, fmaf(qb.y, f2.y, fmaf(qb.z, f3.x, fmaf(qb.w, f3.y, acc))))))));
}

__global__ void __launch_bounds__(256) dsqg_fwd(
    const float* __restrict__ q, const float* __restrict__ pb,
    const float* __restrict__ se, float* __restrict__ out)
{
    constexpr int offs[NOFF] = {1,2,3,4,5,6,7,8,9,11,13,15,16,23,32,64,128,256,512,1024};

    __shared__ __align__(16) __half2 se_h[NOFF * HDIM / 2];   // fp16 scale_embed (5KB)
    __shared__ unsigned long long red2[WARPS][8][10];         // transpose reduce (A rows 0-3, B rows 4-7)
    __shared__ __align__(16) float p_s[WARPS][2][20];         // softmax weights per query
    __shared__ float pb_s[NOFF];

    const int tid  = threadIdx.x;
    const int w    = tid >> 5;
    const int l    = tid & 31;
    const int half = l >> 4;          // 0 -> query A, 1 -> query B
    const int m16  = l & 15;          // dim slice: halfs [8*m16, 8*m16+8)

    const int bid = blockIdx.x;
    const int bh  = bid >> 7;
    const int n0  = (bid & 127) * 64;
    const int h   = bh & (NH - 1);

    for (int i = tid; i < NOFF * HDIM / 2; i += 256) {
        float2 f = ((const float2*)se)[i];
        se_h[i] = __float22half2_rn(f);
    }
    if (tid < NOFF) pb_s[tid] = pb[tid * NH + h];
    __syncthreads();

    const float sc = 0.088388347648318447f;      // 1/sqrt(128)
    const size_t base = (size_t)bh * SEQN * HDIM;
    const __half* kb = g_kh + base;
    const __half* vb = g_vh + base;

    for (int it = 0; it < ITERS; ++it) {
        const int qA  = n0 + it * (WARPS * 2) + w * 2;   // warp owns queries qA, qA+1
        const int myq = qA + half;

        // q: 8 floats for this lane's dim slice
        const float* qrow = q + base + (size_t)myq * HDIM + m16 * 8;
        const float4 q0 = *(const float4*)qrow;
        const float4 q1 = *(const float4*)(qrow + 4);

        // ---- scores: one LDG.128 serves both queries' k row (adjacent rows) ----
        float acc[NOFF];
#pragma unroll
        for (int j = 0; j < NOFF; ++j) {
            int kp = myq - offs[j]; if (kp < 0) kp = 0;
            const uint4 kk = *(const uint4*)(kb + (size_t)kp * HDIM + m16 * 8);
            const uint4 sh = *(const uint4*)(se_h + j * (HDIM / 2) + m16 * 4);
            uint4 ks;
            ks.x = h2u(__hadd2(*(const __half2*)&kk.x, *(const __half2*)&sh.x));
            ks.y = h2u(__hadd2(*(const __half2*)&kk.y, *(const __half2*)&sh.y));
            ks.z = h2u(__hadd2(*(const __half2*)&kk.z, *(const __half2*)&sh.z));
            ks.w = h2u(__hadd2(*(const __half2*)&kk.w, *(const __half2*)&sh.w));
            acc[j] = 0.f;
            dot8(acc[j], q0, q1, ks);
        }

        // ---- reduce over the 16 lanes of each half (2 shfl rounds + smem transpose) ----
        unsigned long long u[10];
#pragma unroll
        for (int m = 0; m < 10; ++m) u[m] = f2pack(acc[2 * m], acc[2 * m + 1]);
#pragma unroll
        for (int m = 0; m < 10; ++m) u[m] = f2add(u[m], __shfl_xor_sync(0xffffffffu, u[m], 8));
#pragma unroll
        for (int m = 0; m < 10; ++m) u[m] = f2add(u[m], __shfl_xor_sync(0xffffffffu, u[m], 4));
        if (m16 < 4) {
            const int row = (l & 3) | (half << 2);
#pragma unroll
            for (int m = 0; m < 10; ++m) red2[w][row][m] = u[m];
        }
        __syncwarp();

        // ---- per-offset scores -> exp (no max pass: |s| << 88 for normal data) ----
        float eA = 0.f, eB = 0.f;
        if (l < NOFF) {
            const int mm = l >> 1;
            unsigned long long tA = 0ULL, tB = 0ULL;
#pragma unroll
            for (int i = 0; i < 4; ++i) {
                tA = f2add(tA, red2[w][i][mm]);
                tB = f2add(tB, red2[w][i + 4][mm]);
            }
            const float2 fa = f2unpack(tA);
            const float2 fb = f2unpack(tB);
            const float sA = (l & 1) ? fa.y : fa.x;
            const float sB = (l & 1) ? fb.y : fb.x;
            const float pbl = pb_s[l];
            if (qA     >= c_offs[l]) eA = __expf(sA * sc + pbl);
            if (qA + 1 >= c_offs[l]) eB = __expf(sB * sc + pbl);
        }

        // packed butterfly sums both queries at once
        unsigned long long ee = f2pack(eA, eB);
#pragma unroll
        for (int o = 16; o; o >>= 1) ee = f2add(ee, __shfl_xor_sync(0xffffffffu, ee, o));
        const float2 ls = f2unpack(ee);
        if (l < NOFF) {
            p_s[w][0][l] = eA * (ls.x > 0.f ? 1.f / ls.x : 0.f);
            p_s[w][1][l] = eB * (ls.y > 0.f ? 1.f / ls.y : 0.f);
        }
        __syncwarp();

        // ---- output: one LDG.128 serves both queries' v row; p via smem broadcast ----
        float o_[8];
#pragma unroll
        for (int d = 0; d < 8; ++d) o_[d] = 0.f;
#pragma unroll
        for (int g = 0; g < 5; ++g) {
            const float4 p4 = ((const float4*)p_s[w][half])[g];
#pragma unroll
            for (int jj = 0; jj < 4; ++jj) {
                const int j = 4 * g + jj;
                int kp = myq - offs[j]; if (kp < 0) kp = 0;
                const uint4 vv = *(const uint4*)(vb + (size_t)kp * HDIM + m16 * 8);
                const float2 f0 = __half22float2(*(const __half2*)&vv.x);
                const float2 f1 = __half22float2(*(const __half2*)&vv.y);
                const float2 f2 = __half22float2(*(const __half2*)&vv.z);
                const float2 f3 = __half22float2(*(const __half2*)&vv.w);
                const float pj = (jj == 0) ? p4.x : (jj == 1) ? p4.y : (jj == 2) ? p4.z : p4.w;
                o_[0] = fmaf(pj, f0.x, o_[0]);
                o_[1] = fmaf(pj, f0.y, o_[1]);
                o_[2] = fmaf(pj, f1.x, o_[2]);
                o_[3] = fmaf(pj, f1.y, o_[3]);
                o_[4] = fmaf(pj, f2.x, o_[4]);
                o_[5] = fmaf(pj, f2.y, o_[5]);
                o_[6] = fmaf(pj, f3.x, o_[6]);
                o_[7] = fmaf(pj, f3.y, o_[7]);
            }
        }
        float* orow = out + base + (size_t)myq * HDIM + m16 * 8;
        *(float4*)orow       = make_float4(o_[0], o_[1], o_[2], o_[3]);
        *(float4*)(orow + 4) = make_float4(o_[4], o_[5], o_[6], o_[7]);
        __syncwarp();   // red2 / p_s safe for next iteration
    }
}

extern "C" void kernel_launch(void* const* d_in, const int* in_sizes, int n_in,
                              void* d_out, int out_size) {
    const float* q  = (const float*)d_in[0];
    const float* k  = (const float*)d_in[1];
    const float* v  = (const float*)d_in[2];
    const float* pb = (const float*)d_in[3];
    const float* se = (const float*)d_in[4];
    (void)in_sizes; (void)n_in; (void)out_size;

    cvt_kv<<<8192, 256>>>(k, v);                              // fp32 -> fp16 mirrors
    dsqg_fwd<<<NB * NH * (SEQN / 64), 256>>>(q, pb, se, (float*)d_out);
}

// round 10
// speedup vs baseline: 1.3690x; 1.3690x over previous
#include <cuda_runtime.h>
#include <cuda_fp16.h>
#include <math.h>
#include <float.h>

#define NOFF 20
#define HDIM 128
#define SEQN 8192
#define NH   16
#define NB   2
#define WARPS 8
#define QPW   8                        // queries per warp -> 64 queries/block
#define TOTE (NB * NH * SEQN * HDIM)   // 33554432 elements

__constant__ int c_offs[NOFF] = {1,2,3,4,5,6,7,8,9,11,13,15,16,23,32,64,128,256,512,1024};

// fp16 mirrors of k and v (static device scratch; allocation-free)
__device__ __half g_kh[TOTE];
__device__ __half g_vh[TOTE];

__device__ __forceinline__ unsigned long long f2add(unsigned long long a, unsigned long long b) {
    unsigned long long d;
    asm("add.rn.f32x2 %0, %1, %2;" : "=l"(d) : "l"(a), "l"(b));
    return d;
}
__device__ __forceinline__ unsigned long long f2pack(float lo, float hi) {
    unsigned long long d;
    asm("mov.b64 %0, {%1, %2};" : "=l"(d) : "f"(lo), "f"(hi));
    return d;
}
__device__ __forceinline__ float2 f2unpack(unsigned long long a) {
    float lo, hi;
    asm("mov.b64 {%0, %1}, %2;" : "=f"(lo), "=f"(hi) : "l"(a));
    return make_float2(lo, hi);
}
__device__ __forceinline__ unsigned int h2u(__half2 h) {
    union { __half2 h; unsigned int u; } c; c.h = h; return c.u;
}

// ---- pre-pass: fp32 k,v -> fp16 mirrors (streaming; ~DRAM floor) ----
__global__ void __launch_bounds__(256) cvt_kv(const float* __restrict__ k, const float* __restrict__ v)
{
    const int total4 = TOTE / 4;
    for (int i = blockIdx.x * blockDim.x + threadIdx.x; i < total4; i += gridDim.x * blockDim.x) {
        float4 a = __ldcs(((const float4*)k) + i);
        uint2 ka;
        ka.x = h2u(__floats2half2_rn(a.x, a.y));
        ka.y = h2u(__floats2half2_rn(a.z, a.w));
        ((uint2*)g_kh)[i] = ka;
        float4 b = __ldcs(((const float4*)v) + i);
        uint2 vb2;
        vb2.x = h2u(__floats2half2_rn(b.x, b.y));
        vb2.y = h2u(__floats2half2_rn(b.z, b.w));
        ((uint2*)g_vh)[i] = vb2;
    }
}

__global__ void __launch_bounds__(256) dsqg_fwd(
    const float* __restrict__ q, const float* __restrict__ pb,
    const float* __restrict__ se, float* __restrict__ out)
{
    constexpr int offs[NOFF] = {1,2,3,4,5,6,7,8,9,11,13,15,16,23,32,64,128,256,512,1024};

    __shared__ __align__(16) __half2 se_h[NOFF * HDIM / 2];   // fp16 scale_embed (5KB)
    __shared__ unsigned long long red2[WARPS][8][5];          // rows 0-3: even j, 4-7: odd j
    __shared__ __align__(16) float p_s[WARPS][2][12];         // p by parity, padded
    __shared__ float pb_s[NOFF];

    const int tid  = threadIdx.x;
    const int w    = tid >> 5;
    const int l    = tid & 31;
    const int half = l >> 4;          // offset parity this lane handles
    const int m16  = l & 15;          // dim slice: halfs [8*m16, 8*m16+8)

    const int bid = blockIdx.x;
    const int bh  = bid >> 7;
    const int n0  = (bid & 127) * 64;
    const int h   = bh & (NH - 1);

    for (int i = tid; i < NOFF * HDIM / 2; i += 256) {
        float2 f = ((const float2*)se)[i];
        se_h[i] = __float22half2_rn(f);
    }
    if (tid < NOFF) pb_s[tid] = pb[tid * NH + h];
    __syncthreads();

    const float sc = 0.088388347648318447f;      // 1/sqrt(128)
    const size_t base = (size_t)bh * SEQN * HDIM;
    const __half* kb = g_kh + base;
    const __half* vb = g_vh + base;

    for (int it = 0; it < QPW; ++it) {
        const int n = n0 + it * WARPS + w;       // warp owns query n

        // q: this lane's 8 dims (both halves read the same row; L1 broadcast)
        const float* qrow = q + base + (size_t)n * HDIM + m16 * 8;
        const float4 q0 = *(const float4*)qrow;
        const float4 q1 = *(const float4*)(qrow + 4);

        // ---- scores: lane handles offsets j = 2t + half, t = 0..9 ----
        float acc[10];
#pragma unroll
        for (int t = 0; t < 10; ++t) {
            const int j = 2 * t + half;
            int kp = n - offs[j]; if (kp < 0) kp = 0;
            const uint4 kk = *(const uint4*)(kb + (size_t)kp * HDIM + m16 * 8);
            const uint4 sh = *(const uint4*)(se_h + j * (HDIM / 2) + m16 * 4);
            const float2 f0 = __half22float2(__hadd2(*(const __half2*)&kk.x, *(const __half2*)&sh.x));
            const float2 f1 = __half22float2(__hadd2(*(const __half2*)&kk.y, *(const __half2*)&sh.y));
            const float2 f2 = __half22float2(__hadd2(*(const __half2*)&kk.z, *(const __half2*)&sh.z));
            const float2 f3 = __half22float2(__hadd2(*(const __half2*)&kk.w, *(const __half2*)&sh.w));
            acc[t] = fmaf(q0.x, f0.x, fmaf(q0.y, f0.y, fmaf(q0.z, f1.x, fmaf(q0.w, f1.y,
                     fmaf(q1.x, f2.x, fmaf(q1.y, f2.y, fmaf(q1.z, f3.x, q1.w * f3.y)))))));
        }

        // ---- reduce over 16 lanes of each half: 2 packed shfl rounds + smem ----
        unsigned long long u[5];
#pragma unroll
        for (int m = 0; m < 5; ++m) u[m] = f2pack(acc[2 * m], acc[2 * m + 1]);
#pragma unroll
        for (int m = 0; m < 5; ++m) u[m] = f2add(u[m], __shfl_xor_sync(0xffffffffu, u[m], 8));
#pragma unroll
        for (int m = 0; m < 5; ++m) u[m] = f2add(u[m], __shfl_xor_sync(0xffffffffu, u[m], 4));
        if (m16 < 4) {
            const int row = (half << 2) | m16;
#pragma unroll
            for (int m = 0; m < 5; ++m) red2[w][row][m] = u[m];
        }
        __syncwarp();

        // ---- per-offset score -> exp (no max pass; scores are O(10)) ----
        float e = 0.f;
        if (l < NOFF) {
            const int rb = (l & 1) << 2;         // parity selects row group
            const int wd = l >> 2;               // packed word = t>>1, t = l>>1
            unsigned long long tsum = 0ULL;
#pragma unroll
            for (int i = 0; i < 4; ++i) tsum = f2add(tsum, red2[w][rb + i][wd]);
            const float2 tp = f2unpack(tsum);
            const float s = (((l >> 1) & 1) ? tp.y : tp.x) * sc + pb_s[l];
            if (n >= c_offs[l]) e = __expf(s);
        }
        float lsum = e;
#pragma unroll
        for (int o = 16; o; o >>= 1) lsum += __shfl_xor_sync(0xffffffffu, lsum, o);
        if (l < NOFF) p_s[w][l & 1][l >> 1] = e * (lsum > 0.f ? 1.f / lsum : 0.f);
        __syncwarp();

        // ---- output: lane accumulates its parity's offsets, then cross-half merge ----
        float o_[8];
#pragma unroll
        for (int d = 0; d < 8; ++d) o_[d] = 0.f;
        const float4 pA = ((const float4*)p_s[w][half])[0];   // t 0..3
        const float4 pB = ((const float4*)p_s[w][half])[1];   // t 4..7
        const float2 pC = ((const float2*)p_s[w][half])[4];   // t 8..9
#pragma unroll
        for (int t = 0; t < 10; ++t) {
            const int j = 2 * t + half;
            int kp = n - offs[j]; if (kp < 0) kp = 0;
            const uint4 vv = *(const uint4*)(vb + (size_t)kp * HDIM + m16 * 8);
            const float2 f0 = __half22float2(*(const __half2*)&vv.x);
            const float2 f1 = __half22float2(*(const __half2*)&vv.y);
            const float2 f2 = __half22float2(*(const __half2*)&vv.z);
            const float2 f3 = __half22float2(*(const __half2*)&vv.w);
            const float pj = (t < 4) ? ((t == 0) ? pA.x : (t == 1) ? pA.y : (t == 2) ? pA.z : pA.w)
                          : (t < 8) ? ((t == 4) ? pB.x : (t == 5) ? pB.y : (t == 6) ? pB.z : pB.w)
                                    : ((t == 8) ? pC.x : pC.y);
            o_[0] = fmaf(pj, f0.x, o_[0]);
            o_[1] = fmaf(pj, f0.y, o_[1]);
            o_[2] = fmaf(pj, f1.x, o_[2]);
            o_[3] = fmaf(pj, f1.y, o_[3]);
            o_[4] = fmaf(pj, f2.x, o_[4]);
            o_[5] = fmaf(pj, f2.y, o_[5]);
            o_[6] = fmaf(pj, f3.x, o_[6]);
            o_[7] = fmaf(pj, f3.y, o_[7]);
        }
        // merge even/odd partials across halves (packed shfl)
        unsigned long long ou[4];
#pragma unroll
        for (int m = 0; m < 4; ++m) {
            ou[m] = f2pack(o_[2 * m], o_[2 * m + 1]);
            ou[m] = f2add(ou[m], __shfl_xor_sync(0xffffffffu, ou[m], 16));
        }
        // half 0 stores dims [m16*8, +4), half 1 stores [m16*8+4, +8)
        const float2 a0 = f2unpack(ou[half * 2]);
        const float2 a1 = f2unpack(ou[half * 2 + 1]);
        *(float4*)(out + base + (size_t)n * HDIM + m16 * 8 + half * 4) =
            make_float4(a0.x, a0.y, a1.x, a1.y);
        __syncwarp();   // red2 / p_s safe for next iteration
    }
}

extern "C" void kernel_launch(void* const* d_in, const int* in_sizes, int n_in,
                              void* d_out, int out_size) {
    const float* q  = (const float*)d_in[0];
    const float* k  = (const float*)d_in[1];
    const float* v  = (const float*)d_in[2];
    const float* pb = (const float*)d_in[3];
    const float* se = (const float*)d_in[4];
    (void)in_sizes; (void)n_in; (void)out_size;

    cvt_kv<<<8192, 256>>>(k, v);                              // fp32 -> fp16 mirrors
    dsqg_fwd<<<NB * NH * (SEQN / 64), 256>>>(q, pb, se, (float*)d_out);
}